// round 16
// baseline (speedup 1.0000x reference)
#include <cuda_runtime.h>
#include <cuda_bf16.h>
#include <cstdint>
#include <math.h>

// Problem dims
#define BSZ   16
#define HH    64
#define WWID  64
#define CDIM  512
#define NHEAD 8
#define DKK   64
#define DVV   64
#define PIX   4096
#define MROWS 65536

// ---------------- scratch (device globals; no runtime allocation) ----------
__device__ float g_partial[BSZ * 32 * CDIM];
__device__ float g_qW[BSZ * NHEAD * CDIM];
__device__ float g_S[BSZ * NHEAD * PIX];
__device__ float g_ah[BSZ * HH * NHEAD * WWID];
__device__ float g_av[BSZ * WWID * NHEAD * HH];
__device__ float g_yh[(size_t)NHEAD * BSZ * HH * CDIM];
__device__ float g_yv[(size_t)NHEAD * BSZ * WWID * CDIM];
__device__ float g_Ah[BSZ * NHEAD * HH * DVV];
__device__ float g_Av[BSZ * NHEAD * WWID * DVV];
__device__ __nv_bfloat16 g_Aext[(size_t)MROWS * 192];  // [Ahi | Alo | Ahi]
__device__ __nv_bfloat16 g_Wext[192 * 512];            // [Whi ; Whi ; Wlo]

__device__ __forceinline__ uint32_t smem_u32(const void* p) {
    uint32_t a;
    asm("{ .reg .u64 t; cvta.to.shared.u64 t, %1; cvt.u32.u64 %0, t; }"
        : "=r"(a) : "l"(p));
    return a;
}
__device__ __forceinline__ uint32_t f2tf32(float f) {
    uint32_t r;
    asm("cvt.rna.tf32.f32 %0, %1;" : "=r"(r) : "f"(f));
    return r;
}
__device__ __forceinline__ void mma_tf32(
    float* c, const uint32_t* a, const uint32_t* b)
{
    asm volatile(
        "mma.sync.aligned.m16n8k8.row.col.f32.tf32.tf32.f32 "
        "{%0,%1,%2,%3}, {%4,%5,%6,%7}, {%8,%9}, {%0,%1,%2,%3};"
        : "+f"(c[0]), "+f"(c[1]), "+f"(c[2]), "+f"(c[3])
        : "r"(a[0]), "r"(a[1]), "r"(a[2]), "r"(a[3]), "r"(b[0]), "r"(b[1]));
}

// ---------------- 1) spatial mean pooling ----------------------------------
__global__ __launch_bounds__(512) void pool_kernel(const float* __restrict__ x) {
    int b = blockIdx.x, j = blockIdx.y, c = threadIdx.x;
    const float* xp = x + ((size_t)b * PIX + (size_t)j * 128) * CDIM + c;
    float s = 0.f;
#pragma unroll 8
    for (int p = 0; p < 128; p++) s += xp[(size_t)p * CDIM];
    g_partial[(b * 32 + j) * CDIM + c] = s;
}

// ---------------- 2) fused q + qW -------------------------------------------
// block b, 512 thr. q[b] computed entirely here, then qW from smem.
__global__ __launch_bounds__(512) void qqw_kernel(
    const float* __restrict__ Wq, const float* __restrict__ bq,
    const float* __restrict__ Wk)
{
    int b = blockIdx.x, t = threadIdx.x;
    __shared__ float sp[CDIM];
    __shared__ float sq[CDIM];
    float s = 0.f;
#pragma unroll
    for (int j = 0; j < 32; j++) s += g_partial[(b * 32 + j) * CDIM + t];
    sp[t] = s * (1.0f / 4096.0f);
    __syncthreads();
    float acc = bq[t];
#pragma unroll 8
    for (int c = 0; c < CDIM; c++) acc += sp[c] * Wq[c * 512 + t];
    sq[t] = acc;
    __syncthreads();
    // qW[b,n,t] = 0.125 * sum_k sq[n*64+k] * Wk[t, n*64+k]
    const float* wr = Wk + (size_t)t * 512;
    float a[8] = {0.f, 0.f, 0.f, 0.f, 0.f, 0.f, 0.f, 0.f};
#pragma unroll
    for (int n = 0; n < 8; n++)
#pragma unroll 8
        for (int k = 0; k < 64; k++)
            a[n] += sq[n * 64 + k] * wr[n * 64 + k];
#pragma unroll
    for (int n = 0; n < 8; n++)
        g_qW[(b * 8 + n) * 512 + t] = a[n] * 0.125f;
}

// ---------------- 3) scores: cp.async double-buffered (round-14 proven) ----
__global__ __launch_bounds__(128) void score_kernel(const float* __restrict__ x) {
    extern __shared__ float sdyn[];
    float* sqw = sdyn;                  // [8][512] = 16KB
    float* xs0 = sdyn + 4096;           // [128][36]
    float* xs1 = xs0 + 128 * 36;        // [128][36]
    int b = blockIdx.x, tid = threadIdx.x;
    int p0 = blockIdx.y * 128;

    for (int i = tid; i < 4096; i += 128)
        sqw[i] = g_qW[(size_t)b * 4096 + i];

    const float* xbase = x + ((size_t)b * PIX + p0) * CDIM;
    int pr = tid >> 3, cc = (tid & 7) * 4;

#pragma unroll
    for (int i = 0; i < 8; i++) {
        int p = pr + i * 16;
        uint32_t d = smem_u32(xs0 + p * 36 + cc);
        const float* s = xbase + (size_t)p * CDIM + cc;
        asm volatile("cp.async.ca.shared.global [%0], [%1], 16;"
                     :: "r"(d), "l"(s));
    }
    asm volatile("cp.async.commit_group;");

    float acc[8] = {0.f, 0.f, 0.f, 0.f, 0.f, 0.f, 0.f, 0.f};

    for (int ch = 0; ch < 16; ch++) {
        float* cur = (ch & 1) ? xs1 : xs0;
        float* nxt = (ch & 1) ? xs0 : xs1;
        if (ch + 1 < 16) {
#pragma unroll
            for (int i = 0; i < 8; i++) {
                int p = pr + i * 16;
                uint32_t d = smem_u32(nxt + p * 36 + cc);
                const float* s = xbase + (size_t)p * CDIM + (ch + 1) * 32 + cc;
                asm volatile("cp.async.ca.shared.global [%0], [%1], 16;"
                             :: "r"(d), "l"(s));
            }
            asm volatile("cp.async.commit_group;");
            asm volatile("cp.async.wait_group 1;");
        } else {
            asm volatile("cp.async.wait_group 0;");
        }
        __syncthreads();
#pragma unroll
        for (int c4 = 0; c4 < 8; c4++) {
            float4 xv = *(const float4*)(cur + tid * 36 + c4 * 4);
#pragma unroll
            for (int n = 0; n < 8; n++) {
                float4 w = *(const float4*)(sqw + n * 512 + ch * 32 + c4 * 4);
                acc[n] += xv.x * w.x + xv.y * w.y + xv.z * w.z + xv.w * w.w;
            }
        }
        __syncthreads();
    }
#pragma unroll
    for (int n = 0; n < 8; n++)
        g_S[(size_t)(b * 8 + n) * PIX + p0 + tid] = acc[n];
}

// ---------------- 4) dual softmax per (b,n), write transposed layouts ------
__global__ __launch_bounds__(256) void softmax_kernel() {
    int bn = blockIdx.x;
    int b = bn >> 3, n = bn & 7;
    int tid = threadIdx.x, w = tid >> 5, l = tid & 31;
    __shared__ float ss[4096];
    for (int i = tid; i < 4096; i += 256) ss[i] = g_S[(size_t)bn * 4096 + i];
    __syncthreads();

    for (int h = w; h < 64; h += 8) {
        float x0 = ss[h * 64 + l], x1 = ss[h * 64 + 32 + l];
        float m = fmaxf(x0, x1);
#pragma unroll
        for (int o = 16; o > 0; o >>= 1)
            m = fmaxf(m, __shfl_xor_sync(0xffffffffu, m, o));
        float e0 = __expf(x0 - m), e1 = __expf(x1 - m);
        float sum = e0 + e1;
#pragma unroll
        for (int o = 16; o > 0; o >>= 1)
            sum += __shfl_xor_sync(0xffffffffu, sum, o);
        float inv = 1.0f / sum;
        float* dst = g_ah + ((size_t)(b * 64 + h) * 8 + n) * 64;
        dst[l] = e0 * inv;
        dst[32 + l] = e1 * inv;
    }

    if (tid < 64) {
        int c = tid;
        float m = -1e30f;
#pragma unroll 8
        for (int h = 0; h < 64; h++) m = fmaxf(m, ss[h * 64 + c]);
        float sum = 0.f;
#pragma unroll 8
        for (int h = 0; h < 64; h++) sum += __expf(ss[h * 64 + c] - m);
        float inv = 1.0f / sum;
        float* dst = g_av + ((size_t)(b * 64 + c) * 8 + n) * 64;
#pragma unroll 8
        for (int h = 0; h < 64; h++)
            dst[h] = __expf(ss[h * 64 + c] - m) * inv;
    }
}

// ---------------- 5) y_h / y_v: weighted sums; grid ordered for L2 reuse ---
__global__ __launch_bounds__(128) void y_kernel(const float* __restrict__ x) {
    int s = blockIdx.x, path = blockIdx.y, b = blockIdx.z;
    int tid = threadIdx.x;
    __shared__ float sa[512];
    const float* asrc = (path ? g_av : g_ah) + (size_t)(b * 64 + s) * 512;
    for (int i = tid; i < 512; i += 128) sa[i] = asrc[i];
    __syncthreads();

    size_t base = (size_t)b * PIX * CDIM +
                  (path ? (size_t)s * CDIM : (size_t)s * 64 * CDIM);
    size_t stride4 = (path ? (size_t)64 * CDIM : (size_t)CDIM) / 4;
    const float4* xp = (const float4*)(x) + base / 4 + tid;

    float4 acc[8];
#pragma unroll
    for (int n = 0; n < 8; n++) acc[n] = make_float4(0.f, 0.f, 0.f, 0.f);

#pragma unroll 8
    for (int j = 0; j < 64; j++) {
        float4 xv = xp[j * stride4];
#pragma unroll
        for (int n = 0; n < 8; n++) {
            float f = sa[n * 64 + j];
            acc[n].x += f * xv.x;
            acc[n].y += f * xv.y;
            acc[n].z += f * xv.z;
            acc[n].w += f * xv.w;
        }
    }
    float* yout = path ? g_yv : g_yh;
#pragma unroll
    for (int n = 0; n < 8; n++)
        ((float4*)(yout + ((size_t)(n * 1024 + b * 64 + s)) * 512))[tid] = acc[n];
}

// ---------------- 6) aproj via tf32 mma: A = Y @ Wv_n + bv ------------------
__global__ __launch_bounds__(256) void aproj_tf32(
    const float* __restrict__ Wv, const float* __restrict__ bv)
{
    __shared__ float sY[64 * 36];
    __shared__ float sW[32 * 72];
    int n = blockIdx.x, b = blockIdx.y, path = blockIdx.z;
    const float* Y = (path ? g_yv : g_yh) + ((size_t)(n * 1024 + b * 64)) * 512;
    float* outp = (path ? g_Av : g_Ah) + (size_t)(b * 8 + n) * 4096;

    int tid = threadIdx.x, lane = tid & 31, wid = tid >> 5;
    int wm = wid >> 1;
    int wnb = (wid & 1) * 32;
    int lr = lane >> 2, lc = lane & 3;

    float acc[4][4];
#pragma unroll
    for (int i = 0; i < 4; i++)
#pragma unroll
        for (int j = 0; j < 4; j++) acc[i][j] = 0.f;

    for (int k0 = 0; k0 < 512; k0 += 32) {
#pragma unroll
        for (int i = 0; i < 2; i++) {
            int idx = tid + i * 256;
            int r = idx >> 3, c4 = idx & 7;
            *(float4*)(sY + r * 36 + c4 * 4) =
                *(const float4*)(Y + (size_t)r * 512 + k0 + c4 * 4);
        }
#pragma unroll
        for (int i = 0; i < 2; i++) {
            int idx = tid + i * 256;
            int r = idx >> 4, c4 = idx & 15;
            *(float4*)(sW + r * 72 + c4 * 4) =
                *(const float4*)(Wv + (size_t)(k0 + r) * 512 + n * 64 + c4 * 4);
        }
        __syncthreads();

#pragma unroll
        for (int ks = 0; ks < 4; ks++) {
            int kk = ks * 8;
            float a0 = sY[(wm * 16 + lr) * 36 + kk + lc];
            float a1 = sY[(wm * 16 + lr + 8) * 36 + kk + lc];
            float a2 = sY[(wm * 16 + lr) * 36 + kk + lc + 4];
            float a3 = sY[(wm * 16 + lr + 8) * 36 + kk + lc + 4];
            uint32_t ahi[4] = {f2tf32(a0), f2tf32(a1), f2tf32(a2), f2tf32(a3)};
            uint32_t alo[4] = {
                f2tf32(a0 - __uint_as_float(ahi[0])),
                f2tf32(a1 - __uint_as_float(ahi[1])),
                f2tf32(a2 - __uint_as_float(ahi[2])),
                f2tf32(a3 - __uint_as_float(ahi[3]))};
#pragma unroll
            for (int nt = 0; nt < 4; nt++) {
                int nb = wnb + nt * 8;
                float b0 = sW[(kk + lc) * 72 + nb + lr];
                float b1 = sW[(kk + lc + 4) * 72 + nb + lr];
                uint32_t bhi[2] = {f2tf32(b0), f2tf32(b1)};
                uint32_t blo[2] = {
                    f2tf32(b0 - __uint_as_float(bhi[0])),
                    f2tf32(b1 - __uint_as_float(bhi[1]))};
                mma_tf32(acc[nt], ahi, bhi);
                mma_tf32(acc[nt], alo, bhi);
                mma_tf32(acc[nt], ahi, blo);
            }
        }
        __syncthreads();
    }

#pragma unroll
    for (int nt = 0; nt < 4; nt++) {
        int col = wnb + nt * 8 + lc * 2;
        float b0 = bv[n * 64 + col], b1 = bv[n * 64 + col + 1];
        int r0 = wm * 16 + lr;
        *(float2*)(outp + (size_t)r0 * 64 + col) =
            make_float2(acc[nt][0] + b0, acc[nt][1] + b1);
        *(float2*)(outp + (size_t)(r0 + 8) * 64 + col) =
            make_float2(acc[nt][2] + b0, acc[nt][3] + b1);
    }
}

// ---------------- 7) Wext = [hi(Wo); hi(Wo); lo(Wo)] -----------------------
__global__ void wext_kernel(const float* __restrict__ Wo) {
    int r = blockIdx.x, n = threadIdx.x;
    int src = (r < 128) ? (r & 63) : (r - 128);
    float v = Wo[(size_t)src * 512 + n];
    __nv_bfloat16 hi = __float2bfloat16(v);
    g_Wext[r * 512 + n] = (r < 128) ? hi
                                    : __float2bfloat16(v - __bfloat162float(hi));
}

// ---------------- 8) combine -> Aext bf16 [hi|lo|hi] ------------------------
__global__ __launch_bounds__(512) void combine_kernel() {
    int b = blockIdx.x >> 6, h = blockIdx.x & 63;
    int tid = threadIdx.x;
    __shared__ float sAh[NHEAD * DVV];
    {
        int n = tid >> 6, v = tid & 63;
        sAh[tid] = g_Ah[((size_t)(b * 8 + n) * 64 + h) * 64 + v];
    }
    __syncthreads();
    int v = tid & 63, wg = tid >> 6;
    for (int wc = wg; wc < 64; wc += 8) {
        float acc = 0.f;
#pragma unroll
        for (int n = 0; n < NHEAD; n++)
            acc += sAh[n * 64 + v] *
                   g_Av[((size_t)(b * 8 + n) * 64 + wc) * 64 + v];
        size_t row = ((size_t)(b * 64 + h)) * 64 + wc;
        __nv_bfloat16 hi = __float2bfloat16(acc);
        __nv_bfloat16 lo = __float2bfloat16(acc - __bfloat162float(hi));
        g_Aext[row * 192 + v]       = hi;
        g_Aext[row * 192 + 64 + v]  = lo;
        g_Aext[row * 192 + 128 + v] = hi;
    }
}

// ---------------- 9) bf16 mma GEMM with cp.async double buffering ----------
#define OUT_A_ELE (128 * 72)
#define OUT_B_ELE (64 * 136)
#define OUT_SMEM  ((OUT_A_ELE + OUT_B_ELE) * 2 * 2)   // 2 stages, bf16

__global__ __launch_bounds__(256) void mma_gemm_out(
    const float* __restrict__ bias, float* __restrict__ C)
{
    extern __shared__ __align__(16) char smo[];
    __nv_bfloat16* smA[2] = {(__nv_bfloat16*)smo,
                             (__nv_bfloat16*)smo + OUT_A_ELE};
    __nv_bfloat16* smB[2] = {(__nv_bfloat16*)smo + 2 * OUT_A_ELE,
                             (__nv_bfloat16*)smo + 2 * OUT_A_ELE + OUT_B_ELE};
    int tid = threadIdx.x, lane = tid & 31, wid = tid >> 5;
    int wm = wid >> 2, wn = wid & 3;
    size_t m0 = (size_t)blockIdx.y * 128;
    int n0 = blockIdx.x * 128;

    float acc[4][4][4];
#pragma unroll
    for (int i = 0; i < 4; i++)
#pragma unroll
        for (int j = 0; j < 4; j++)
#pragma unroll
            for (int k = 0; k < 4; k++) acc[i][j][k] = 0.f;

#pragma unroll
    for (int i = 0; i < 4; i++) {
        int idx = tid + i * 256;
        int r = idx >> 3, c8 = idx & 7;
        uint32_t d = smem_u32(smA[0] + r * 72 + c8 * 8);
        const __nv_bfloat16* s = g_Aext + (m0 + r) * 192 + c8 * 8;
        asm volatile("cp.async.ca.shared.global [%0], [%1], 16;"
                     :: "r"(d), "l"(s));
        int rb = idx >> 4, cb8 = idx & 15;
        uint32_t db = smem_u32(smB[0] + rb * 136 + cb8 * 8);
        const __nv_bfloat16* sb = g_Wext + (size_t)rb * 512 + n0 + cb8 * 8;
        asm volatile("cp.async.ca.shared.global [%0], [%1], 16;"
                     :: "r"(db), "l"(sb));
    }
    asm volatile("cp.async.commit_group;");

    for (int ki = 0; ki < 3; ki++) {
        int cur = ki & 1, nxt = cur ^ 1;
        if (ki + 1 < 3) {
            int kc = (ki + 1) * 64;
#pragma unroll
            for (int i = 0; i < 4; i++) {
                int idx = tid + i * 256;
                int r = idx >> 3, c8 = idx & 7;
                uint32_t d = smem_u32(smA[nxt] + r * 72 + c8 * 8);
                const __nv_bfloat16* s = g_Aext + (m0 + r) * 192 + kc + c8 * 8;
                asm volatile("cp.async.ca.shared.global [%0], [%1], 16;"
                             :: "r"(d), "l"(s));
                int rb = idx >> 4, cb8 = idx & 15;
                uint32_t db = smem_u32(smB[nxt] + rb * 136 + cb8 * 8);
                const __nv_bfloat16* sb = g_Wext + (size_t)(kc + rb) * 512 + n0 + cb8 * 8;
                asm volatile("cp.async.ca.shared.global [%0], [%1], 16;"
                             :: "r"(db), "l"(sb));
            }
            asm volatile("cp.async.commit_group;");
            asm volatile("cp.async.wait_group 1;");
        } else {
            asm volatile("cp.async.wait_group 0;");
        }
        __syncthreads();

#pragma unroll
        for (int ks = 0; ks < 4; ks++) {
            uint32_t af[4][4];
#pragma unroll
            for (int mi = 0; mi < 4; mi++) {
                uint32_t addr = smem_u32(
                    smA[cur] + (wm * 64 + mi * 16 + (lane & 15)) * 72 +
                    ks * 16 + (lane >> 4) * 8);
                asm volatile(
                    "ldmatrix.sync.aligned.m8n8.x4.shared.b16 {%0,%1,%2,%3}, [%4];"
                    : "=r"(af[mi][0]), "=r"(af[mi][1]),
                      "=r"(af[mi][2]), "=r"(af[mi][3])
                    : "r"(addr));
            }
            uint32_t bfr[2][4];
#pragma unroll
            for (int bi = 0; bi < 2; bi++) {
                int nb = wn * 32 + bi * 16;
                uint32_t addr = smem_u32(
                    smB[cur] + (ks * 16 + (lane & 7) + ((lane >> 3) & 1) * 8) * 136 +
                    nb + (lane >> 4) * 8);
                asm volatile(
                    "ldmatrix.sync.aligned.m8n8.x4.trans.shared.b16 {%0,%1,%2,%3}, [%4];"
                    : "=r"(bfr[bi][0]), "=r"(bfr[bi][1]),
                      "=r"(bfr[bi][2]), "=r"(bfr[bi][3])
                    : "r"(addr));
            }
#pragma unroll
            for (int mi = 0; mi < 4; mi++) {
#pragma unroll
                for (int ni = 0; ni < 4; ni++) {
                    uint32_t b0 = bfr[ni >> 1][(ni & 1) * 2];
                    uint32_t b1 = bfr[ni >> 1][(ni & 1) * 2 + 1];
                    asm volatile(
                        "mma.sync.aligned.m16n8k16.row.col.f32.bf16.bf16.f32 "
                        "{%0,%1,%2,%3}, {%4,%5,%6,%7}, {%8,%9}, {%0,%1,%2,%3};"
                        : "+f"(acc[mi][ni][0]), "+f"(acc[mi][ni][1]),
                          "+f"(acc[mi][ni][2]), "+f"(acc[mi][ni][3])
                        : "r"(af[mi][0]), "r"(af[mi][1]),
                          "r"(af[mi][2]), "r"(af[mi][3]),
                          "r"(b0), "r"(b1));
                }
            }
        }
        __syncthreads();
    }

    int g = lane >> 2, t = lane & 3;
#pragma unroll
    for (int mi = 0; mi < 4; mi++) {
#pragma unroll
        for (int ni = 0; ni < 4; ni++) {
            size_t row = m0 + wm * 64 + mi * 16 + g;
            int col = n0 + wn * 32 + ni * 8 + t * 2;
            float b0 = bias[col], b1 = bias[col + 1];
            float2 o0 = {acc[mi][ni][0] + b0, acc[mi][ni][1] + b1};
            float2 o1 = {acc[mi][ni][2] + b0, acc[mi][ni][3] + b1};
            *(float2*)(C + row * 512 + col) = o0;
            *(float2*)(C + (row + 8) * 512 + col) = o1;
        }
    }
}

// ---------------- launch ----------------------------------------------------
extern "C" void kernel_launch(void* const* d_in, const int* in_sizes, int n_in,
                              void* d_out, int out_size) {
    const float* x  = (const float*)d_in[0];
    const float* Wq = (const float*)d_in[1];
    const float* bq = (const float*)d_in[2];
    const float* Wk = (const float*)d_in[3];
    const float* bk = (const float*)d_in[4];  (void)bk;  // cancels in softmax
    const float* Wv = (const float*)d_in[5];
    const float* bv = (const float*)d_in[6];
    const float* Wo = (const float*)d_in[7];
    const float* bo = (const float*)d_in[8];
    float* out = (float*)d_out;

    const int SCORE_SMEM = (4096 + 2 * 128 * 36) * 4;   // 53248 B
    cudaFuncSetAttribute(score_kernel,
                         cudaFuncAttributeMaxDynamicSharedMemorySize, SCORE_SMEM);
    cudaFuncSetAttribute(mma_gemm_out,
                         cudaFuncAttributeMaxDynamicSharedMemorySize, OUT_SMEM);

    pool_kernel<<<dim3(BSZ, 32), 512>>>(x);
    qqw_kernel<<<BSZ, 512>>>(Wq, bq, Wk);
    score_kernel<<<dim3(BSZ, 32), 128, SCORE_SMEM>>>(x);
    softmax_kernel<<<BSZ * NHEAD, 256>>>();
    y_kernel<<<dim3(64, 2, BSZ), 128>>>(x);
    aproj_tf32<<<dim3(NHEAD, BSZ, 2), 256>>>(Wv, bv);
    combine_kernel<<<BSZ * HH, 512>>>();
    wext_kernel<<<192, 512>>>(Wo);
    mma_gemm_out<<<dim3(4, 512), 256, OUT_SMEM>>>(bo, out);
}

// round 17
// speedup vs baseline: 1.3759x; 1.3759x over previous
#include <cuda_runtime.h>
#include <cuda_bf16.h>
#include <cstdint>
#include <math.h>

// Problem dims
#define BSZ   16
#define HH    64
#define WWID  64
#define CDIM  512
#define NHEAD 8
#define DKK   64
#define DVV   64
#define PIX   4096
#define MROWS 65536

// ---------------- scratch (device globals; no runtime allocation) ----------
__device__ float g_partial[BSZ * 32 * CDIM];
__device__ float g_q[BSZ * NHEAD * DKK];
__device__ float g_qW[BSZ * NHEAD * CDIM];
__device__ float g_S[BSZ * NHEAD * PIX];
__device__ float g_ah[BSZ * HH * NHEAD * WWID];
__device__ float g_av[BSZ * WWID * NHEAD * HH];
__device__ float g_yh[(size_t)NHEAD * BSZ * HH * CDIM];
__device__ float g_yv[(size_t)NHEAD * BSZ * WWID * CDIM];
__device__ float g_Ah[BSZ * NHEAD * HH * DVV];
__device__ float g_Av[BSZ * NHEAD * WWID * DVV];
__device__ __nv_bfloat16 g_Aext[(size_t)MROWS * 128];  // [Ahi | Alo]
__device__ __nv_bfloat16 g_Wext[192 * 512];            // [Whi ; Whi ; Wlo]

__device__ __forceinline__ uint32_t smem_u32(const void* p) {
    uint32_t a;
    asm("{ .reg .u64 t; cvta.to.shared.u64 t, %1; cvt.u32.u64 %0, t; }"
        : "=r"(a) : "l"(p));
    return a;
}
__device__ __forceinline__ uint32_t f2tf32(float f) {
    uint32_t r;
    asm("cvt.rna.tf32.f32 %0, %1;" : "=r"(r) : "f"(f));
    return r;
}
__device__ __forceinline__ void mma_tf32(
    float* c, const uint32_t* a, const uint32_t* b)
{
    asm volatile(
        "mma.sync.aligned.m16n8k8.row.col.f32.tf32.tf32.f32 "
        "{%0,%1,%2,%3}, {%4,%5,%6,%7}, {%8,%9}, {%0,%1,%2,%3};"
        : "+f"(c[0]), "+f"(c[1]), "+f"(c[2]), "+f"(c[3])
        : "r"(a[0]), "r"(a[1]), "r"(a[2]), "r"(a[3]), "r"(b[0]), "r"(b[1]));
}

// ---------------- 1) spatial mean pooling ----------------------------------
__global__ __launch_bounds__(512) void pool_kernel(const float* __restrict__ x) {
    int b = blockIdx.x, j = blockIdx.y, c = threadIdx.x;
    const float* xp = x + ((size_t)b * PIX + (size_t)j * 128) * CDIM + c;
    float s = 0.f;
#pragma unroll 8
    for (int p = 0; p < 128; p++) s += xp[(size_t)p * CDIM];
    g_partial[(b * 32 + j) * CDIM + c] = s;
}

// ---------------- 2) q = pooled @ Wq + bq -----------------------------------
__global__ void q_kernel(const float* __restrict__ Wq, const float* __restrict__ bq) {
    int b = blockIdx.x, t = threadIdx.x;
    __shared__ float sp[CDIM];
    float s = 0.f;
#pragma unroll
    for (int j = 0; j < 32; j++) s += g_partial[(b * 32 + j) * CDIM + t];
    sp[t] = s * (1.0f / 4096.0f);
    __syncthreads();
    float acc = bq[t];
#pragma unroll 8
    for (int c = 0; c < CDIM; c++) acc += sp[c] * Wq[c * 512 + t];
    g_q[b * 512 + t] = acc;
}

// ---------------- 3) qW[b,n,c] = scale * sum_k Wk[c, n*64+k] q[b,n,k] ------
__global__ void qw_kernel(const float* __restrict__ Wk) {
    int b = blockIdx.x, n = blockIdx.y, c = threadIdx.x;
    __shared__ float sq[64];
    if (c < 64) sq[c] = g_q[b * 512 + n * 64 + c];
    __syncthreads();
    const float* wr = Wk + (size_t)c * 512 + n * 64;
    float acc = 0.f;
#pragma unroll
    for (int k = 0; k < 64; k++) acc += sq[k] * wr[k];
    g_qW[(b * 8 + n) * 512 + c] = acc * 0.125f;
}

// ---------------- 4) scores: cp.async double-buffered (proven) -------------
__global__ __launch_bounds__(128) void score_kernel(const float* __restrict__ x) {
    extern __shared__ float sdyn[];
    float* sqw = sdyn;                  // [8][512] = 16KB
    float* xs0 = sdyn + 4096;           // [128][36]
    float* xs1 = xs0 + 128 * 36;        // [128][36]
    int b = blockIdx.x, tid = threadIdx.x;
    int p0 = blockIdx.y * 128;

    for (int i = tid; i < 4096; i += 128)
        sqw[i] = g_qW[(size_t)b * 4096 + i];

    const float* xbase = x + ((size_t)b * PIX + p0) * CDIM;
    int pr = tid >> 3, cc = (tid & 7) * 4;

#pragma unroll
    for (int i = 0; i < 8; i++) {
        int p = pr + i * 16;
        uint32_t d = smem_u32(xs0 + p * 36 + cc);
        const float* s = xbase + (size_t)p * CDIM + cc;
        asm volatile("cp.async.ca.shared.global [%0], [%1], 16;"
                     :: "r"(d), "l"(s));
    }
    asm volatile("cp.async.commit_group;");

    float acc[8] = {0.f, 0.f, 0.f, 0.f, 0.f, 0.f, 0.f, 0.f};

    for (int ch = 0; ch < 16; ch++) {
        float* cur = (ch & 1) ? xs1 : xs0;
        float* nxt = (ch & 1) ? xs0 : xs1;
        if (ch + 1 < 16) {
#pragma unroll
            for (int i = 0; i < 8; i++) {
                int p = pr + i * 16;
                uint32_t d = smem_u32(nxt + p * 36 + cc);
                const float* s = xbase + (size_t)p * CDIM + (ch + 1) * 32 + cc;
                asm volatile("cp.async.ca.shared.global [%0], [%1], 16;"
                             :: "r"(d), "l"(s));
            }
            asm volatile("cp.async.commit_group;");
            asm volatile("cp.async.wait_group 1;");
        } else {
            asm volatile("cp.async.wait_group 0;");
        }
        __syncthreads();
#pragma unroll
        for (int c4 = 0; c4 < 8; c4++) {
            float4 xv = *(const float4*)(cur + tid * 36 + c4 * 4);
#pragma unroll
            for (int n = 0; n < 8; n++) {
                float4 w = *(const float4*)(sqw + n * 512 + ch * 32 + c4 * 4);
                acc[n] += xv.x * w.x + xv.y * w.y + xv.z * w.z + xv.w * w.w;
            }
        }
        __syncthreads();
    }
#pragma unroll
    for (int n = 0; n < 8; n++)
        g_S[(size_t)(b * 8 + n) * PIX + p0 + tid] = acc[n];
}

// ---------------- 5) dual softmax per (b,n), write transposed layouts ------
__global__ __launch_bounds__(256) void softmax_kernel() {
    int bn = blockIdx.x;
    int b = bn >> 3, n = bn & 7;
    int tid = threadIdx.x, w = tid >> 5, l = tid & 31;
    __shared__ float ss[4096];
    for (int i = tid; i < 4096; i += 256) ss[i] = g_S[(size_t)bn * 4096 + i];
    __syncthreads();

    for (int h = w; h < 64; h += 8) {
        float x0 = ss[h * 64 + l], x1 = ss[h * 64 + 32 + l];
        float m = fmaxf(x0, x1);
#pragma unroll
        for (int o = 16; o > 0; o >>= 1)
            m = fmaxf(m, __shfl_xor_sync(0xffffffffu, m, o));
        float e0 = __expf(x0 - m), e1 = __expf(x1 - m);
        float sum = e0 + e1;
#pragma unroll
        for (int o = 16; o > 0; o >>= 1)
            sum += __shfl_xor_sync(0xffffffffu, sum, o);
        float inv = 1.0f / sum;
        float* dst = g_ah + ((size_t)(b * 64 + h) * 8 + n) * 64;
        dst[l] = e0 * inv;
        dst[32 + l] = e1 * inv;
    }

    if (tid < 64) {
        int c = tid;
        float m = -1e30f;
#pragma unroll 8
        for (int h = 0; h < 64; h++) m = fmaxf(m, ss[h * 64 + c]);
        float sum = 0.f;
#pragma unroll 8
        for (int h = 0; h < 64; h++) sum += __expf(ss[h * 64 + c] - m);
        float inv = 1.0f / sum;
        float* dst = g_av + ((size_t)(b * 64 + c) * 8 + n) * 64;
#pragma unroll 8
        for (int h = 0; h < 64; h++)
            dst[h] = __expf(ss[h * 64 + c] - m) * inv;
    }
}

// ---------------- 6) y_h / y_v: weighted sums; grid ordered for L2 reuse ---
__global__ __launch_bounds__(128) void y_kernel(const float* __restrict__ x) {
    int s = blockIdx.x, path = blockIdx.y, b = blockIdx.z;
    int tid = threadIdx.x;
    __shared__ float sa[512];
    const float* asrc = (path ? g_av : g_ah) + (size_t)(b * 64 + s) * 512;
    for (int i = tid; i < 512; i += 128) sa[i] = asrc[i];
    __syncthreads();

    size_t base = (size_t)b * PIX * CDIM +
                  (path ? (size_t)s * CDIM : (size_t)s * 64 * CDIM);
    size_t stride4 = (path ? (size_t)64 * CDIM : (size_t)CDIM) / 4;
    const float4* xp = (const float4*)(x) + base / 4 + tid;

    float4 acc[8];
#pragma unroll
    for (int n = 0; n < 8; n++) acc[n] = make_float4(0.f, 0.f, 0.f, 0.f);

#pragma unroll 8
    for (int j = 0; j < 64; j++) {
        float4 xv = xp[j * stride4];
#pragma unroll
        for (int n = 0; n < 8; n++) {
            float f = sa[n * 64 + j];
            acc[n].x += f * xv.x;
            acc[n].y += f * xv.y;
            acc[n].z += f * xv.z;
            acc[n].w += f * xv.w;
        }
    }
    float* yout = path ? g_yv : g_yh;
#pragma unroll
    for (int n = 0; n < 8; n++)
        ((float4*)(yout + ((size_t)(n * 1024 + b * 64 + s)) * 512))[tid] = acc[n];
}

// ---------------- 7) aproj via tf32 mma: A = Y @ Wv_n + bv ------------------
__global__ __launch_bounds__(256) void aproj_tf32(
    const float* __restrict__ Wv, const float* __restrict__ bv)
{
    __shared__ float sY[64 * 36];
    __shared__ float sW[32 * 72];
    int n = blockIdx.x, b = blockIdx.y, path = blockIdx.z;
    const float* Y = (path ? g_yv : g_yh) + ((size_t)(n * 1024 + b * 64)) * 512;
    float* outp = (path ? g_Av : g_Ah) + (size_t)(b * 8 + n) * 4096;

    int tid = threadIdx.x, lane = tid & 31, wid = tid >> 5;
    int wm = wid >> 1;
    int wnb = (wid & 1) * 32;
    int lr = lane >> 2, lc = lane & 3;

    float acc[4][4];
#pragma unroll
    for (int i = 0; i < 4; i++)
#pragma unroll
        for (int j = 0; j < 4; j++) acc[i][j] = 0.f;

    for (int k0 = 0; k0 < 512; k0 += 32) {
#pragma unroll
        for (int i = 0; i < 2; i++) {
            int idx = tid + i * 256;
            int r = idx >> 3, c4 = idx & 7;
            *(float4*)(sY + r * 36 + c4 * 4) =
                *(const float4*)(Y + (size_t)r * 512 + k0 + c4 * 4);
        }
#pragma unroll
        for (int i = 0; i < 2; i++) {
            int idx = tid + i * 256;
            int r = idx >> 4, c4 = idx & 15;
            *(float4*)(sW + r * 72 + c4 * 4) =
                *(const float4*)(Wv + (size_t)(k0 + r) * 512 + n * 64 + c4 * 4);
        }
        __syncthreads();

#pragma unroll
        for (int ks = 0; ks < 4; ks++) {
            int kk = ks * 8;
            float a0 = sY[(wm * 16 + lr) * 36 + kk + lc];
            float a1 = sY[(wm * 16 + lr + 8) * 36 + kk + lc];
            float a2 = sY[(wm * 16 + lr) * 36 + kk + lc + 4];
            float a3 = sY[(wm * 16 + lr + 8) * 36 + kk + lc + 4];
            uint32_t ahi[4] = {f2tf32(a0), f2tf32(a1), f2tf32(a2), f2tf32(a3)};
            uint32_t alo[4] = {
                f2tf32(a0 - __uint_as_float(ahi[0])),
                f2tf32(a1 - __uint_as_float(ahi[1])),
                f2tf32(a2 - __uint_as_float(ahi[2])),
                f2tf32(a3 - __uint_as_float(ahi[3]))};
#pragma unroll
            for (int nt = 0; nt < 4; nt++) {
                int nb = wnb + nt * 8;
                float b0 = sW[(kk + lc) * 72 + nb + lr];
                float b1 = sW[(kk + lc + 4) * 72 + nb + lr];
                uint32_t bhi[2] = {f2tf32(b0), f2tf32(b1)};
                uint32_t blo[2] = {
                    f2tf32(b0 - __uint_as_float(bhi[0])),
                    f2tf32(b1 - __uint_as_float(bhi[1]))};
                mma_tf32(acc[nt], ahi, bhi);
                mma_tf32(acc[nt], alo, bhi);
                mma_tf32(acc[nt], ahi, blo);
            }
        }
        __syncthreads();
    }

#pragma unroll
    for (int nt = 0; nt < 4; nt++) {
        int col = wnb + nt * 8 + lc * 2;
        float b0 = bv[n * 64 + col], b1 = bv[n * 64 + col + 1];
        int r0 = wm * 16 + lr;
        *(float2*)(outp + (size_t)r0 * 64 + col) =
            make_float2(acc[nt][0] + b0, acc[nt][1] + b1);
        *(float2*)(outp + (size_t)(r0 + 8) * 64 + col) =
            make_float2(acc[nt][2] + b0, acc[nt][3] + b1);
    }
}

// ---------------- 8) Wext = [hi(Wo); hi(Wo); lo(Wo)] -----------------------
__global__ void wext_kernel(const float* __restrict__ Wo) {
    int r = blockIdx.x, n = threadIdx.x;
    int src = (r < 128) ? (r & 63) : (r - 128);
    float v = Wo[(size_t)src * 512 + n];
    __nv_bfloat16 hi = __float2bfloat16(v);
    g_Wext[r * 512 + n] = (r < 128) ? hi
                                    : __float2bfloat16(v - __bfloat162float(hi));
}

// ---------------- 9) combine -> Aext bf16 [hi|lo] ---------------------------
__global__ __launch_bounds__(512) void combine_kernel() {
    int b = blockIdx.x >> 6, h = blockIdx.x & 63;
    int tid = threadIdx.x;
    __shared__ float sAh[NHEAD * DVV];
    {
        int n = tid >> 6, v = tid & 63;
        sAh[tid] = g_Ah[((size_t)(b * 8 + n) * 64 + h) * 64 + v];
    }
    __syncthreads();
    int v = tid & 63, wg = tid >> 6;
    for (int wc = wg; wc < 64; wc += 8) {
        float acc = 0.f;
#pragma unroll
        for (int n = 0; n < NHEAD; n++)
            acc += sAh[n * 64 + v] *
                   g_Av[((size_t)(b * 8 + n) * 64 + wc) * 64 + v];
        size_t row = ((size_t)(b * 64 + h)) * 64 + wc;
        __nv_bfloat16 hi = __float2bfloat16(acc);
        __nv_bfloat16 lo = __float2bfloat16(acc - __bfloat162float(hi));
        g_Aext[row * 128 + v]      = hi;
        g_Aext[row * 128 + 64 + v] = lo;
    }
}

// ---------------- 10) bf16 mma GEMM, A chunks {hi,lo,hi}, cp.async 2-stage --
#define OUT_A_ELE (128 * 72)
#define OUT_B_ELE (64 * 136)
#define OUT_SMEM  ((OUT_A_ELE + OUT_B_ELE) * 2 * 2)   // 2 stages, bf16

__global__ __launch_bounds__(256) void mma_gemm_out(
    const float* __restrict__ bias, float* __restrict__ C)
{
    extern __shared__ __align__(16) char smo[];
    __nv_bfloat16* smA[2] = {(__nv_bfloat16*)smo,
                             (__nv_bfloat16*)smo + OUT_A_ELE};
    __nv_bfloat16* smB[2] = {(__nv_bfloat16*)smo + 2 * OUT_A_ELE,
                             (__nv_bfloat16*)smo + 2 * OUT_A_ELE + OUT_B_ELE};
    int tid = threadIdx.x, lane = tid & 31, wid = tid >> 5;
    int wm = wid >> 2, wn = wid & 3;
    size_t m0 = (size_t)blockIdx.y * 128;
    int n0 = blockIdx.x * 128;
    const int AOFF[3] = {0, 64, 0};   // terms: Ahi*Whi, Alo*Whi, Ahi*Wlo

    float acc[4][4][4];
#pragma unroll
    for (int i = 0; i < 4; i++)
#pragma unroll
        for (int j = 0; j < 4; j++)
#pragma unroll
            for (int k = 0; k < 4; k++) acc[i][j][k] = 0.f;

#pragma unroll
    for (int i = 0; i < 4; i++) {
        int idx = tid + i * 256;
        int r = idx >> 3, c8 = idx & 7;
        uint32_t d = smem_u32(smA[0] + r * 72 + c8 * 8);
        const __nv_bfloat16* s = g_Aext + (m0 + r) * 128 + c8 * 8;
        asm volatile("cp.async.ca.shared.global [%0], [%1], 16;"
                     :: "r"(d), "l"(s));
        int rb = idx >> 4, cb8 = idx & 15;
        uint32_t db = smem_u32(smB[0] + rb * 136 + cb8 * 8);
        const __nv_bfloat16* sb = g_Wext + (size_t)rb * 512 + n0 + cb8 * 8;
        asm volatile("cp.async.ca.shared.global [%0], [%1], 16;"
                     :: "r"(db), "l"(sb));
    }
    asm volatile("cp.async.commit_group;");

    for (int ki = 0; ki < 3; ki++) {
        int cur = ki & 1, nxt = cur ^ 1;
        if (ki + 1 < 3) {
            int kcB = (ki + 1) * 64;
            int kcA = AOFF[ki + 1];
#pragma unroll
            for (int i = 0; i < 4; i++) {
                int idx = tid + i * 256;
                int r = idx >> 3, c8 = idx & 7;
                uint32_t d = smem_u32(smA[nxt] + r * 72 + c8 * 8);
                const __nv_bfloat16* s = g_Aext + (m0 + r) * 128 + kcA + c8 * 8;
                asm volatile("cp.async.ca.shared.global [%0], [%1], 16;"
                             :: "r"(d), "l"(s));
                int rb = idx >> 4, cb8 = idx & 15;
                uint32_t db = smem_u32(smB[nxt] + rb * 136 + cb8 * 8);
                const __nv_bfloat16* sb = g_Wext + (size_t)(kcB + rb) * 512 + n0 + cb8 * 8;
                asm volatile("cp.async.ca.shared.global [%0], [%1], 16;"
                             :: "r"(db), "l"(sb));
            }
            asm volatile("cp.async.commit_group;");
            asm volatile("cp.async.wait_group 1;");
        } else {
            asm volatile("cp.async.wait_group 0;");
        }
        __syncthreads();

#pragma unroll
        for (int ks = 0; ks < 4; ks++) {
            uint32_t af[4][4];
#pragma unroll
            for (int mi = 0; mi < 4; mi++) {
                uint32_t addr = smem_u32(
                    smA[cur] + (wm * 64 + mi * 16 + (lane & 15)) * 72 +
                    ks * 16 + (lane >> 4) * 8);
                asm volatile(
                    "ldmatrix.sync.aligned.m8n8.x4.shared.b16 {%0,%1,%2,%3}, [%4];"
                    : "=r"(af[mi][0]), "=r"(af[mi][1]),
                      "=r"(af[mi][2]), "=r"(af[mi][3])
                    : "r"(addr));
            }
            uint32_t bfr[2][4];
#pragma unroll
            for (int bi = 0; bi < 2; bi++) {
                int nb = wn * 32 + bi * 16;
                uint32_t addr = smem_u32(
                    smB[cur] + (ks * 16 + (lane & 7) + ((lane >> 3) & 1) * 8) * 136 +
                    nb + (lane >> 4) * 8);
                asm volatile(
                    "ldmatrix.sync.aligned.m8n8.x4.trans.shared.b16 {%0,%1,%2,%3}, [%4];"
                    : "=r"(bfr[bi][0]), "=r"(bfr[bi][1]),
                      "=r"(bfr[bi][2]), "=r"(bfr[bi][3])
                    : "r"(addr));
            }
#pragma unroll
            for (int mi = 0; mi < 4; mi++) {
#pragma unroll
                for (int ni = 0; ni < 4; ni++) {
                    uint32_t b0 = bfr[ni >> 1][(ni & 1) * 2];
                    uint32_t b1 = bfr[ni >> 1][(ni & 1) * 2 + 1];
                    asm volatile(
                        "mma.sync.aligned.m16n8k16.row.col.f32.bf16.bf16.f32 "
                        "{%0,%1,%2,%3}, {%4,%5,%6,%7}, {%8,%9}, {%0,%1,%2,%3};"
                        : "+f"(acc[mi][ni][0]), "+f"(acc[mi][ni][1]),
                          "+f"(acc[mi][ni][2]), "+f"(acc[mi][ni][3])
                        : "r"(af[mi][0]), "r"(af[mi][1]),
                          "r"(af[mi][2]), "r"(af[mi][3]),
                          "r"(b0), "r"(b1));
                }
            }
        }
        __syncthreads();
    }

    int g = lane >> 2, t = lane & 3;
#pragma unroll
    for (int mi = 0; mi < 4; mi++) {
#pragma unroll
        for (int ni = 0; ni < 4; ni++) {
            size_t row = m0 + wm * 64 + mi * 16 + g;
            int col = n0 + wn * 32 + ni * 8 + t * 2;
            float b0 = bias[col], b1 = bias[col + 1];
            float2 o0 = {acc[mi][ni][0] + b0, acc[mi][ni][1] + b1};
            float2 o1 = {acc[mi][ni][2] + b0, acc[mi][ni][3] + b1};
            *(float2*)(C + row * 512 + col) = o0;
            *(float2*)(C + (row + 8) * 512 + col) = o1;
        }
    }
}

// ---------------- launch ----------------------------------------------------
extern "C" void kernel_launch(void* const* d_in, const int* in_sizes, int n_in,
                              void* d_out, int out_size) {
    const float* x  = (const float*)d_in[0];
    const float* Wq = (const float*)d_in[1];
    const float* bq = (const float*)d_in[2];
    const float* Wk = (const float*)d_in[3];
    const float* bk = (const float*)d_in[4];  (void)bk;  // cancels in softmax
    const float* Wv = (const float*)d_in[5];
    const float* bv = (const float*)d_in[6];
    const float* Wo = (const float*)d_in[7];
    const float* bo = (const float*)d_in[8];
    float* out = (float*)d_out;

    const int SCORE_SMEM = (4096 + 2 * 128 * 36) * 4;   // 53248 B
    cudaFuncSetAttribute(score_kernel,
                         cudaFuncAttributeMaxDynamicSharedMemorySize, SCORE_SMEM);
    cudaFuncSetAttribute(mma_gemm_out,
                         cudaFuncAttributeMaxDynamicSharedMemorySize, OUT_SMEM);

    pool_kernel<<<dim3(BSZ, 32), 512>>>(x);
    q_kernel<<<BSZ, 512>>>(Wq, bq);
    qw_kernel<<<dim3(BSZ, NHEAD), 512>>>(Wk);
    score_kernel<<<dim3(BSZ, 32), 128, SCORE_SMEM>>>(x);
    softmax_kernel<<<BSZ * NHEAD, 256>>>();
    y_kernel<<<dim3(64, 2, BSZ), 128>>>(x);
    aproj_tf32<<<dim3(NHEAD, BSZ, 2), 256>>>(Wv, bv);
    combine_kernel<<<BSZ * HH, 512>>>();
    wext_kernel<<<192, 512>>>(Wo);
    mma_gemm_out<<<dim3(4, 512), 256, OUT_SMEM>>>(bo, out);
}